// round 2
// baseline (speedup 1.0000x reference)
#include <cuda_runtime.h>
#include <cstdint>

// QuantumLSTM fused persistent kernel.
// T=1024 steps, B=1024 rows, IN=128, H=16, D=IN+H=144.
// Each batch row is an independent recurrence -> no grid sync needed.
// Mapping: 128-thread block owns 8 batch rows for all 1024 steps.
//   2 warps per 4-row group. Within a group's 64 lanes:
//     warp0 lanes 0-15: gate f units 0-15, lanes 16-31: gate i
//     warp1 lanes 0-15: gate g,            lanes 16-31: gate o
//   Each lane keeps its 144-float W row in registers, packed as 72 x f32x2,
//   and accumulates 4 rows with fma.rn.f32x2 (2x fp32 throughput vs FFMA).
// x tile double-buffered in shared with register prefetch of step t+1.

namespace {
constexpr int TT = 1024;
constexpr int BB = 1024;
constexpr int INDIM = 128;
constexpr int HH = 16;
constexpr int DD = 144;
constexpr int ROWS_PER_BLOCK = 8;
constexpr int NBLOCKS = BB / ROWS_PER_BLOCK;  // 128 blocks -> 1 per SM

typedef unsigned long long ull;

__device__ __forceinline__ void ffma2(ull &acc, ull a, ull b) {
    asm("fma.rn.f32x2 %0, %1, %2, %0;" : "+l"(acc) : "l"(a), "l"(b));
}
__device__ __forceinline__ ull packf2(float lo, float hi) {
    ull r;
    asm("mov.b64 %0, {%1, %2};" : "=l"(r) : "f"(lo), "f"(hi));
    return r;
}
__device__ __forceinline__ float2 unpackf2(ull v) {
    float lo, hi;
    asm("mov.b64 {%0, %1}, %2;" : "=f"(lo), "=f"(hi) : "l"(v));
    return make_float2(lo, hi);
}
__device__ __forceinline__ float sigmoid_f(float x) {
    return __fdividef(1.0f, 1.0f + __expf(-x));
}
__device__ __forceinline__ float tanh_f(float x) {
    float u = __expf(-2.0f * x);
    return __fdividef(1.0f - u, 1.0f + u);
}
}  // namespace

__global__ __launch_bounds__(128, 1) void qlstm_kernel(
    const float* __restrict__ X,
    const float* __restrict__ Wf, const float* __restrict__ bf, const float* __restrict__ thf,
    const float* __restrict__ Wi, const float* __restrict__ bi, const float* __restrict__ thi,
    const float* __restrict__ Wg, const float* __restrict__ bg, const float* __restrict__ thg,
    const float* __restrict__ Wo, const float* __restrict__ bo, const float* __restrict__ tho,
    float* __restrict__ out)
{
    __shared__ __align__(16) float xbuf[2][ROWS_PER_BLOCK][INDIM];  // 8 KB
    __shared__ __align__(16) float hbuf[ROWS_PER_BLOCK][HH];
    __shared__ __align__(16) float gbuf[4][ROWS_PER_BLOCK][HH];

    const int tid  = threadIdx.x;
    const int lane = tid & 31;
    const int warp = tid >> 5;   // 0..3
    const int grp  = warp >> 1;  // 0..1 (which 4-row group)
    const int wIn  = warp & 1;   // 0: f/i warp, 1: g/o warp
    const int unit = lane & 15;  // hidden unit 0..15
    const int half = lane >> 4;  // 0/1 within warp
    const int gate = wIn * 2 + half;  // 0=f 1=i 2=g 3=o

    const int rowBase = blockIdx.x * ROWS_PER_BLOCK;

    const float* Wsel = (gate == 0) ? Wf : (gate == 1) ? Wi : (gate == 2) ? Wg : Wo;
    const float* bsel = (gate == 0) ? bf : (gate == 1) ? bi : (gate == 2) ? bg : bo;
    const float* tsel = (gate == 0) ? thf : (gate == 1) ? thi : (gate == 2) ? thg : tho;
    const float bias  = bsel[unit];
    const float theta = tsel[unit];

    // Load this lane's W row (144 floats) into 72 packed f32x2 registers.
    ull w2[DD / 2];
    {
        const float* wrow = Wsel + unit * DD;  // 576-byte offset: 16B aligned
        #pragma unroll
        for (int i = 0; i < DD / 4; ++i) {  // 36 x longlong2
            longlong2 v = reinterpret_cast<const longlong2*>(wrow)[i];
            w2[2 * i]     = (ull)v.x;
            w2[2 * i + 1] = (ull)v.y;
        }
    }

    // Per-thread LSTM cell state for (row = tid>>4, unit = tid&15): private register.
    float creg = 0.0f;
    // Zero h state.
    {
        int row = tid >> 4, u = tid & 15;
        hbuf[row][u] = 0.0f;
    }

    // x staging: thread loads 8 consecutive floats of one row.
    const int ldRow = tid >> 4;   // 0..7
    const int ldSeg = tid & 15;   // 0..15 -> floats [seg*8, seg*8+8)
    {
        const float* gp = X + ((size_t)0 * BB + rowBase + ldRow) * INDIM + ldSeg * 8;
        float4 a = *reinterpret_cast<const float4*>(gp);
        float4 b = *reinterpret_cast<const float4*>(gp + 4);
        float4* dst = reinterpret_cast<float4*>(&xbuf[0][ldRow][ldSeg * 8]);
        dst[0] = a; dst[1] = b;
    }
    __syncthreads();

    int cur = 0;
    for (int t = 0; t < TT; ++t) {
        // Prefetch x(t+1) into registers (latency hidden under compute).
        float4 p0 = make_float4(0.f, 0.f, 0.f, 0.f), p1 = p0;
        if (t + 1 < TT) {
            const float* gp = X + ((size_t)(t + 1) * BB + rowBase + ldRow) * INDIM + ldSeg * 8;
            p0 = *reinterpret_cast<const float4*>(gp);
            p1 = *reinterpret_cast<const float4*>(gp + 4);
        }

        // ---- gate pre-activations: z = b + [x,h] . Wrow ----
        ull accA[4], accB[4];
        #pragma unroll
        for (int m = 0; m < 4; ++m) { accA[m] = packf2(bias, 0.0f); accB[m] = 0ull; }

        #pragma unroll
        for (int kk = 0; kk < INDIM / 4; ++kk) {     // 32 iterations over k-quads
            #pragma unroll
            for (int m = 0; m < 4; ++m) {
                longlong2 xv = *reinterpret_cast<const longlong2*>(
                    &xbuf[cur][grp * 4 + m][kk * 4]);  // LDS.128 broadcast
                ffma2(accA[m], (ull)xv.x, w2[2 * kk]);
                ffma2(accB[m], (ull)xv.y, w2[2 * kk + 1]);
            }
        }
        #pragma unroll
        for (int jj = 0; jj < HH / 2; ++jj) {        // recurrent part, h pairs
            #pragma unroll
            for (int m = 0; m < 4; ++m) {
                ull hv = *reinterpret_cast<const ull*>(&hbuf[grp * 4 + m][jj * 2]);
                if (jj & 1) ffma2(accB[m], hv, w2[INDIM / 2 + jj]);
                else        ffma2(accA[m], hv, w2[INDIM / 2 + jj]);
            }
        }

        // ---- qgate + activation, per row ----
        #pragma unroll
        for (int m = 0; m < 4; ++m) {
            float2 a  = unpackf2(accA[m]);
            float2 b2 = unpackf2(accB[m]);
            float z = (a.x + a.y) + (b2.x + b2.y);
            float s = __sinf(z + theta);
            // inclusive scan over 16-lane segment (units 0..15 of this gate)
            float cs = s;
            #pragma unroll
            for (int d2 = 1; d2 < 16; d2 <<= 1) {
                float v = __shfl_up_sync(0xffffffffu, cs, d2);
                if ((lane & 15) >= d2) cs += v;
            }
            float tot = __shfl_sync(0xffffffffu, cs, lane | 15);  // segment total
            float q = (unit == 0) ? (s + tot) : cs;
            float act = (gate == 2) ? tanh_f(q) : sigmoid_f(q);
            gbuf[gate][grp * 4 + m][unit] = act;
        }
        __syncthreads();

        // ---- cell update: thread (row = tid>>4, unit = tid&15) ----
        {
            int row = tid >> 4, u = tid & 15;
            float fv = gbuf[0][row][u], iv = gbuf[1][row][u];
            float gv = gbuf[2][row][u], ov = gbuf[3][row][u];
            float cn = fv * creg + iv * gv;
            float hn = ov * tanh_f(cn);
            creg = cn;
            hbuf[row][u] = hn;
            out[((size_t)t * BB + rowBase + row) * HH + u] = hn;
        }
        // stage prefetched x(t+1) into the other buffer
        if (t + 1 < TT) {
            float4* dst = reinterpret_cast<float4*>(&xbuf[cur ^ 1][ldRow][ldSeg * 8]);
            dst[0] = p0; dst[1] = p1;
        }
        __syncthreads();
        cur ^= 1;
    }

    // Tail outputs: hT, cT appended after outs.
    {
        int row = tid >> 4, u = tid & 15;
        size_t base = (size_t)TT * BB * HH;
        out[base + (size_t)(rowBase + row) * HH + u] = hbuf[row][u];
        out[base + (size_t)BB * HH + (size_t)(rowBase + row) * HH + u] = creg;
    }
}

extern "C" void kernel_launch(void* const* d_in, const int* in_sizes, int n_in,
                              void* d_out, int out_size) {
    (void)in_sizes; (void)n_in; (void)out_size;
    const float* X   = (const float*)d_in[0];
    const float* Wf  = (const float*)d_in[1];
    const float* bf  = (const float*)d_in[2];
    const float* thf = (const float*)d_in[3];
    const float* Wi  = (const float*)d_in[4];
    const float* bi  = (const float*)d_in[5];
    const float* thi = (const float*)d_in[6];
    const float* Wg  = (const float*)d_in[7];
    const float* bg  = (const float*)d_in[8];
    const float* thg = (const float*)d_in[9];
    const float* Wo  = (const float*)d_in[10];
    const float* bo  = (const float*)d_in[11];
    const float* tho = (const float*)d_in[12];
    float* out = (float*)d_out;

    qlstm_kernel<<<NBLOCKS, 128>>>(X, Wf, bf, thf, Wi, bi, thi,
                                   Wg, bg, thg, Wo, bo, tho, out);
}

// round 4
// speedup vs baseline: 1.5295x; 1.5295x over previous
#include <cuda_runtime.h>
#include <cstdint>

// QuantumLSTM fused persistent kernel, v2: occupancy-doubled.
// T=1024, B=1024, IN=128, H=16, D=144.
// Block = 128 threads = 4 warps, owns 4 batch rows for all 1024 steps.
//   warp w = gate w (0=f 1=i 2=g 3=o)
//   lane = u + 16*p : unit u (0..15), p selects row-pair {2p, 2p+1}
//   Each lane keeps its 144-float W row packed as 72 x f32x2 in registers and
//   accumulates 2 rows with fma.rn.f32x2.
// Grid = 256 blocks, __launch_bounds__(128,2) -> 2 blocks/SM -> 2 warps/SMSP.
// x double-buffered in shared via cp.async (no register staging).

namespace {
constexpr int TT = 1024;
constexpr int BB = 1024;
constexpr int INDIM = 128;
constexpr int HH = 16;
constexpr int DD = 144;
constexpr int RPB = 4;                  // rows per block
constexpr int NBLOCKS = BB / RPB;       // 256
constexpr int XPITCH = INDIM + 4;       // pad: p=0/p=1 LDS.128 pairs 8 banks apart
constexpr int HPITCH = HH + 4;          // pad for ull h reads

typedef unsigned long long ull;

__device__ __forceinline__ void ffma2(ull &acc, ull a, ull b) {
    asm("fma.rn.f32x2 %0, %1, %2, %0;" : "+l"(acc) : "l"(a), "l"(b));
}
__device__ __forceinline__ ull packf2(float lo, float hi) {
    ull r;
    asm("mov.b64 %0, {%1, %2};" : "=l"(r) : "f"(lo), "f"(hi));
    return r;
}
__device__ __forceinline__ float2 unpackf2(ull v) {
    float lo, hi;
    asm("mov.b64 {%0, %1}, %2;" : "=f"(lo), "=f"(hi) : "l"(v));
    return make_float2(lo, hi);
}
__device__ __forceinline__ float sigmoid_f(float x) {
    return __fdividef(1.0f, 1.0f + __expf(-x));
}
__device__ __forceinline__ float tanh_f(float x) {
    float u = __expf(-2.0f * x);
    return __fdividef(1.0f - u, 1.0f + u);
}
__device__ __forceinline__ void cp_async16(uint32_t saddr, const float* g) {
    asm volatile("cp.async.ca.shared.global [%0], [%1], 16;" :: "r"(saddr), "l"(g));
}
}  // namespace

__global__ __launch_bounds__(128, 2) void qlstm_kernel(
    const float* __restrict__ X,
    const float* __restrict__ Wf, const float* __restrict__ bf, const float* __restrict__ thf,
    const float* __restrict__ Wi, const float* __restrict__ bi, const float* __restrict__ thi,
    const float* __restrict__ Wg, const float* __restrict__ bg, const float* __restrict__ thg,
    const float* __restrict__ Wo, const float* __restrict__ bo, const float* __restrict__ tho,
    float* __restrict__ out)
{
    __shared__ __align__(16) float xbuf[2][RPB][XPITCH];   // ~4.2 KB
    __shared__ __align__(16) float hbuf[RPB][HPITCH];
    __shared__ __align__(16) float gbuf[4][RPB][HH];

    const int tid  = threadIdx.x;
    const int lane = tid & 31;
    const int gate = tid >> 5;     // warp index == gate
    const int p    = lane >> 4;    // row-pair selector
    const int u    = lane & 15;    // hidden unit

    const int rowBase = blockIdx.x * RPB;

    const float* Wsel = (gate == 0) ? Wf : (gate == 1) ? Wi : (gate == 2) ? Wg : Wo;
    const float* bsel = (gate == 0) ? bf : (gate == 1) ? bi : (gate == 2) ? bg : bo;
    const float* tsel = (gate == 0) ? thf : (gate == 1) ? thi : (gate == 2) ? thg : tho;
    const float bias  = bsel[u];
    const float theta = tsel[u];

    // W row (144 floats) -> 72 packed f32x2 registers. u*DD*4 = u*576: 16B aligned.
    ull w2[DD / 2];
    {
        const float* wrow = Wsel + u * DD;
        #pragma unroll
        for (int i = 0; i < DD / 4; ++i) {
            longlong2 v = reinterpret_cast<const longlong2*>(wrow)[i];
            w2[2 * i]     = (ull)v.x;
            w2[2 * i + 1] = (ull)v.y;
        }
    }

    // cp.async staging map: thread -> (row = tid>>5, 16B chunk = tid&31)
    const int ldr = tid >> 5;
    const int lds_ = tid & 31;
    uint32_t xsm0 = (uint32_t)__cvta_generic_to_shared(&xbuf[0][ldr][lds_ * 4]);
    uint32_t xsm1 = (uint32_t)__cvta_generic_to_shared(&xbuf[1][ldr][lds_ * 4]);
    const float* xsrc = X + (size_t)(rowBase + ldr) * INDIM + lds_ * 4;
    const size_t xstep = (size_t)BB * INDIM;

    // t=0 tile
    cp_async16(xsm0, xsrc);
    asm volatile("cp.async.commit_group;");

    // init state
    float creg = 0.0f;
    if (tid < RPB * HH) hbuf[tid >> 4][tid & 15] = 0.0f;
    asm volatile("cp.async.wait_group 0;");
    __syncthreads();

    int cur = 0;
    for (int t = 0; t < TT; ++t) {
        // async prefetch x(t+1) into the other buffer
        if (t + 1 < TT) {
            cp_async16(cur ? xsm0 : xsm1, xsrc + (size_t)(t + 1) * xstep);
            asm volatile("cp.async.commit_group;");
        }

        // ---- z = b + [x,h] . Wrow for rows {2p, 2p+1} ----
        ull accA0 = packf2(bias, 0.0f), accB0 = 0ull;
        ull accA1 = packf2(bias, 0.0f), accB1 = 0ull;

        const float* xr0 = &xbuf[cur][2 * p][0];
        const float* xr1 = &xbuf[cur][2 * p + 1][0];
        #pragma unroll
        for (int kk = 0; kk < INDIM / 4; ++kk) {
            longlong2 x0 = *reinterpret_cast<const longlong2*>(xr0 + kk * 4);
            longlong2 x1 = *reinterpret_cast<const longlong2*>(xr1 + kk * 4);
            ffma2(accA0, (ull)x0.x, w2[2 * kk]);
            ffma2(accB0, (ull)x0.y, w2[2 * kk + 1]);
            ffma2(accA1, (ull)x1.x, w2[2 * kk]);
            ffma2(accB1, (ull)x1.y, w2[2 * kk + 1]);
        }
        #pragma unroll
        for (int jj = 0; jj < HH / 2; ++jj) {
            ull h0 = *reinterpret_cast<const ull*>(&hbuf[2 * p][2 * jj]);
            ull h1 = *reinterpret_cast<const ull*>(&hbuf[2 * p + 1][2 * jj]);
            if (jj & 1) { ffma2(accB0, h0, w2[INDIM / 2 + jj]); ffma2(accB1, h1, w2[INDIM / 2 + jj]); }
            else        { ffma2(accA0, h0, w2[INDIM / 2 + jj]); ffma2(accA1, h1, w2[INDIM / 2 + jj]); }
        }

        // ---- qgate + activation (two independent scan chains) ----
        float2 a0 = unpackf2(accA0), b0 = unpackf2(accB0);
        float2 a1 = unpackf2(accA1), b1 = unpackf2(accB1);
        float z0 = (a0.x + a0.y) + (b0.x + b0.y);
        float z1 = (a1.x + a1.y) + (b1.x + b1.y);
        float s0 = __sinf(z0 + theta);
        float s1 = __sinf(z1 + theta);
        float cs0 = s0, cs1 = s1;
        #pragma unroll
        for (int d = 1; d < 16; d <<= 1) {
            float v0 = __shfl_up_sync(0xffffffffu, cs0, d);
            float v1 = __shfl_up_sync(0xffffffffu, cs1, d);
            if (u >= d) { cs0 += v0; cs1 += v1; }
        }
        float tot0 = __shfl_sync(0xffffffffu, cs0, lane | 15);
        float tot1 = __shfl_sync(0xffffffffu, cs1, lane | 15);
        float q0 = (u == 0) ? (s0 + tot0) : cs0;
        float q1 = (u == 0) ? (s1 + tot1) : cs1;
        float act0 = (gate == 2) ? tanh_f(q0) : sigmoid_f(q0);
        float act1 = (gate == 2) ? tanh_f(q1) : sigmoid_f(q1);
        gbuf[gate][2 * p][u]     = act0;
        gbuf[gate][2 * p + 1][u] = act1;
        __syncthreads();

        // ---- cell update: 64 cells, thread = row*16 + u ----
        if (tid < RPB * HH) {
            int row = tid >> 4, uu = tid & 15;
            float fv = gbuf[0][row][uu], iv = gbuf[1][row][uu];
            float gv = gbuf[2][row][uu], ov = gbuf[3][row][uu];
            float cn = fv * creg + iv * gv;
            float hn = ov * tanh_f(cn);
            creg = cn;
            hbuf[row][uu] = hn;
            out[((size_t)t * BB + rowBase + row) * HH + uu] = hn;
        }
        if (t + 1 < TT) asm volatile("cp.async.wait_group 0;");
        __syncthreads();
        cur ^= 1;
    }

    // Tail: hT then cT after outs.
    if (tid < RPB * HH) {
        int row = tid >> 4, uu = tid & 15;
        size_t base = (size_t)TT * BB * HH;
        out[base + (size_t)(rowBase + row) * HH + uu] = hbuf[row][uu];
        out[base + (size_t)BB * HH + (size_t)(rowBase + row) * HH + uu] = creg;
    }
}

extern "C" void kernel_launch(void* const* d_in, const int* in_sizes, int n_in,
                              void* d_out, int out_size) {
    (void)in_sizes; (void)n_in; (void)out_size;
    const float* X   = (const float*)d_in[0];
    const float* Wf  = (const float*)d_in[1];
    const float* bf  = (const float*)d_in[2];
    const float* thf = (const float*)d_in[3];
    const float* Wi  = (const float*)d_in[4];
    const float* bi  = (const float*)d_in[5];
    const float* thi = (const float*)d_in[6];
    const float* Wg  = (const float*)d_in[7];
    const float* bg  = (const float*)d_in[8];
    const float* thg = (const float*)d_in[9];
    const float* Wo  = (const float*)d_in[10];
    const float* bo  = (const float*)d_in[11];
    const float* tho = (const float*)d_in[12];
    float* out = (float*)d_out;

    qlstm_kernel<<<NBLOCKS, 128>>>(X, Wf, bf, thf, Wi, bi, thi,
                                   Wg, bg, thg, Wo, bo, tho, out);
}

// round 5
// speedup vs baseline: 1.6035x; 1.0484x over previous
#include <cuda_runtime.h>
#include <cstdint>

// QuantumLSTM fused persistent kernel, v3: K-split for 4 warps/SMSP.
// T=1024, B=1024, IN=128, H=16, D=144.
// Block = 128 threads = 4 warps, owns RPB=2 batch rows for all 1024 steps.
//   warp w = gate w (0=f 1=i 2=g 3=o)
//   lane = u + 16*khalf : unit u (0..15), khalf selects K-half [0,72) or [72,144)
//   Each lane holds HALF a W row (72 floats = 36 x f32x2 regs) and accumulates
//   BOTH rows over its K-half; shfl_xor(16) merges halves, then the two khalf
//   halves scan the two rows in one shared shfl chain.
// Grid = 512 blocks, __launch_bounds__(128,4) -> 3-4 blocks/SM -> 3-4 warps/SMSP.
// [x|h] unified per-row buffer; x double-buffered via cp.async; h written to
// both buffers by the update warp.

namespace {
constexpr int TT = 1024;
constexpr int BB = 1024;
constexpr int INDIM = 128;
constexpr int HH = 16;
constexpr int DD = 144;
constexpr int KH = DD / 2;              // 72 floats per lane
constexpr int RPB = 2;                  // rows per block
constexpr int NBLOCKS = BB / RPB;       // 512
constexpr int CPITCH = 176;             // floats per row buffer (16B-aligned pad)

typedef unsigned long long ull;

__device__ __forceinline__ void ffma2(ull &acc, ull a, ull b) {
    asm("fma.rn.f32x2 %0, %1, %2, %0;" : "+l"(acc) : "l"(a), "l"(b));
}
__device__ __forceinline__ float2 unpackf2(ull v) {
    float lo, hi;
    asm("mov.b64 {%0, %1}, %2;" : "=f"(lo), "=f"(hi) : "l"(v));
    return make_float2(lo, hi);
}
__device__ __forceinline__ float sigmoid_f(float x) {
    return __fdividef(1.0f, 1.0f + __expf(-x));
}
__device__ __forceinline__ float tanh_f(float x) {
    float u = __expf(-2.0f * x);
    return __fdividef(1.0f - u, 1.0f + u);
}
__device__ __forceinline__ void cp_async16(uint32_t saddr, const float* g) {
    asm volatile("cp.async.ca.shared.global [%0], [%1], 16;" :: "r"(saddr), "l"(g));
}
}  // namespace

__global__ __launch_bounds__(128, 4) void qlstm_kernel(
    const float* __restrict__ X,
    const float* __restrict__ Wf, const float* __restrict__ bf, const float* __restrict__ thf,
    const float* __restrict__ Wi, const float* __restrict__ bi, const float* __restrict__ thi,
    const float* __restrict__ Wg, const float* __restrict__ bg, const float* __restrict__ thg,
    const float* __restrict__ Wo, const float* __restrict__ bo, const float* __restrict__ tho,
    float* __restrict__ out)
{
    __shared__ __align__(16) float comb[2][RPB][CPITCH];  // [buf][row][ x(128) | h(16) | pad ]
    __shared__ __align__(16) float gbuf[4][RPB][HH];

    const int tid   = threadIdx.x;
    const int lane  = tid & 31;
    const int gate  = tid >> 5;     // warp index == gate
    const int khalf = lane >> 4;    // K-half selector
    const int u     = lane & 15;    // hidden unit

    const int rowBase = blockIdx.x * RPB;

    const float* Wsel = (gate == 0) ? Wf : (gate == 1) ? Wi : (gate == 2) ? Wg : Wo;
    const float* bsel = (gate == 0) ? bf : (gate == 1) ? bi : (gate == 2) ? bg : bo;
    const float* tsel = (gate == 0) ? thf : (gate == 1) ? thi : (gate == 2) ? thg : tho;
    const float bias  = bsel[u];
    const float theta = tsel[u];

    // Half W row (72 floats) -> 36 packed f32x2 regs.
    // Byte offset (u*144 + khalf*72)*4 = 576u + 288*khalf : 16B aligned.
    ull w2[KH / 2];
    {
        const float* wrow = Wsel + u * DD + khalf * KH;
        #pragma unroll
        for (int i = 0; i < KH / 4; ++i) {  // 18 x longlong2
            longlong2 v = reinterpret_cast<const longlong2*>(wrow)[i];
            w2[2 * i]     = (ull)v.x;
            w2[2 * i + 1] = (ull)v.y;
        }
    }

    // x staging: threads 0..63 each own one 16B chunk: row = tid>>5, chunk = tid&31.
    const int ldr = tid >> 5;       // valid when tid < 64
    const int ldc = tid & 31;
    uint32_t xsm0 = (uint32_t)__cvta_generic_to_shared(&comb[0][ldr & 1][ldc * 4]);
    uint32_t xsm1 = (uint32_t)__cvta_generic_to_shared(&comb[1][ldr & 1][ldc * 4]);
    const float* xsrc = X + (size_t)(rowBase + (ldr & 1)) * INDIM + ldc * 4;
    const size_t xstep = (size_t)BB * INDIM;

    // t=0 tile + zero h in both buffers.
    if (tid < 64) {
        cp_async16(xsm0, xsrc);
        asm volatile("cp.async.commit_group;");
    }
    if (tid < 2 * HH) {
        comb[0][tid >> 4][INDIM + (tid & 15)] = 0.0f;
        comb[1][tid >> 4][INDIM + (tid & 15)] = 0.0f;
    }
    float creg = 0.0f;  // cell state: warp0 lane = row*16+u
    asm volatile("cp.async.wait_group 0;");
    __syncthreads();

    int cur = 0;
    for (int t = 0; t < TT; ++t) {
        if (tid < 64 && t + 1 < TT) {
            cp_async16(cur ? xsm0 : xsm1, xsrc + (size_t)(t + 1) * xstep);
            asm volatile("cp.async.commit_group;");
        }

        // ---- partial z for both rows over this lane's K-half ----
        const float* c0 = &comb[cur][0][khalf * KH];
        const float* c1 = &comb[cur][1][khalf * KH];
        ull a0 = 0ull, b0 = 0ull, a1 = 0ull, b1 = 0ull;
        #pragma unroll
        for (int kk = 0; kk < KH / 4; ++kk) {  // 18 iters, 2 LDS.128, 4 ffma2
            longlong2 x0 = *reinterpret_cast<const longlong2*>(c0 + kk * 4);
            longlong2 x1 = *reinterpret_cast<const longlong2*>(c1 + kk * 4);
            ffma2(a0, (ull)x0.x, w2[2 * kk]);
            ffma2(b0, (ull)x0.y, w2[2 * kk + 1]);
            ffma2(a1, (ull)x1.x, w2[2 * kk]);
            ffma2(b1, (ull)x1.y, w2[2 * kk + 1]);
        }
        float2 fa0 = unpackf2(a0), fb0 = unpackf2(b0);
        float2 fa1 = unpackf2(a1), fb1 = unpackf2(b1);
        float z0p = (fa0.x + fa0.y) + (fb0.x + fb0.y);
        float z1p = (fa1.x + fa1.y) + (fb1.x + fb1.y);

        // merge K-halves; lane keeps row = khalf
        float z0 = z0p + __shfl_xor_sync(0xffffffffu, z0p, 16);
        float z1 = z1p + __shfl_xor_sync(0xffffffffu, z1p, 16);
        float z  = (khalf ? z1 : z0) + bias;

        // ---- qgate: sin + 16-segment scan (both rows in one chain) ----
        float s = __sinf(z + theta);
        float cs = s;
        #pragma unroll
        for (int d = 1; d < 16; d <<= 1) {
            float v = __shfl_up_sync(0xffffffffu, cs, d);
            if (u >= d) cs += v;
        }
        float tot = __shfl_sync(0xffffffffu, cs, lane | 15);
        float q = (u == 0) ? (s + tot) : cs;
        float act = (gate == 2) ? tanh_f(q) : sigmoid_f(q);
        gbuf[gate][khalf][u] = act;
        __syncthreads();

        // ---- cell update: 32 cells on warp 0 (lane = row*16 + u) ----
        if (tid < RPB * HH) {
            int row = tid >> 4, uu = tid & 15;
            float fv = gbuf[0][row][uu], iv = gbuf[1][row][uu];
            float gv = gbuf[2][row][uu], ov = gbuf[3][row][uu];
            float cn = fv * creg + iv * gv;
            float hn = ov * tanh_f(cn);
            creg = cn;
            comb[0][row][INDIM + uu] = hn;   // h visible in both x buffers
            comb[1][row][INDIM + uu] = hn;
            out[((size_t)t * BB + rowBase + row) * HH + uu] = hn;
        }
        if (t + 1 < TT) asm volatile("cp.async.wait_group 0;");
        __syncthreads();
        cur ^= 1;
    }

    // Tail: hT then cT after outs.
    if (tid < RPB * HH) {
        int row = tid >> 4, uu = tid & 15;
        size_t base = (size_t)TT * BB * HH;
        out[base + (size_t)(rowBase + row) * HH + uu] = comb[0][row][INDIM + uu];
        out[base + (size_t)BB * HH + (size_t)(rowBase + row) * HH + uu] = creg;
    }
}

extern "C" void kernel_launch(void* const* d_in, const int* in_sizes, int n_in,
                              void* d_out, int out_size) {
    (void)in_sizes; (void)n_in; (void)out_size;
    const float* X   = (const float*)d_in[0];
    const float* Wf  = (const float*)d_in[1];
    const float* bf  = (const float*)d_in[2];
    const float* thf = (const float*)d_in[3];
    const float* Wi  = (const float*)d_in[4];
    const float* bi  = (const float*)d_in[5];
    const float* thi = (const float*)d_in[6];
    const float* Wg  = (const float*)d_in[7];
    const float* bg  = (const float*)d_in[8];
    const float* thg = (const float*)d_in[9];
    const float* Wo  = (const float*)d_in[10];
    const float* bo  = (const float*)d_in[11];
    const float* tho = (const float*)d_in[12];
    float* out = (float*)d_out;

    qlstm_kernel<<<NBLOCKS, 128>>>(X, Wf, bf, thf, Wi, bi, thi,
                                   Wg, bg, thg, Wo, bo, tho, out);
}